// round 1
// baseline (speedup 1.0000x reference)
#include <cuda_runtime.h>

#define BATCH  4
#define SEQ    4096
#define DMODEL 1024
#define HSZ    64
#define NROWS  (BATCH*SEQ)

// Scratch for projected Q/K/V (device globals: no allocation allowed)
__device__ float g_q[NROWS*HSZ];
__device__ float g_k[NROWS*HSZ];
__device__ float g_v[NROWS*HSZ];

// ---- packed fp32x2 helpers (Blackwell; ptxas won't auto-fuse, must use PTX) ----
static __device__ __forceinline__ unsigned long long pk2(float lo, float hi){
    unsigned long long r;
    asm("mov.b64 %0, {%1,%2};" : "=l"(r) : "f"(lo), "f"(hi));
    return r;
}
static __device__ __forceinline__ float2 up2(unsigned long long v){
    float2 f;
    asm("mov.b64 {%0,%1}, %2;" : "=f"(f.x), "=f"(f.y) : "l"(v));
    return f;
}
static __device__ __forceinline__ unsigned long long fma2(unsigned long long a,
                                                          unsigned long long b,
                                                          unsigned long long c){
    unsigned long long d;
    asm("fma.rn.f32x2 %0, %1, %2, %3;" : "=l"(d) : "l"(a), "l"(b), "l"(c));
    return d;
}
static __device__ __forceinline__ unsigned long long mul2(unsigned long long a,
                                                          unsigned long long b){
    unsigned long long d;
    asm("mul.rn.f32x2 %0, %1, %2;" : "=l"(d) : "l"(a), "l"(b));
    return d;
}

// ============================================================================
// Projection: out[n, h] = sum_d x[n, d] * W[d, h]   for W in {Wq, Wk, Wv}
// grid (NROWS/128, 3), block 256. Tile: 128 rows x 64 cols, K-chunk 32.
// ============================================================================
__global__ __launch_bounds__(256, 1) void proj_kernel(
    const float* __restrict__ x, const float* __restrict__ Wq,
    const float* __restrict__ Wk, const float* __restrict__ Wv)
{
    __shared__ float xsT[32][132];   // [k][row] transposed; stride 132 (16B-aligned rows, bank-spread)
    __shared__ float ws[32][64];     // [k][col]

    const int rt0 = blockIdx.x * 128;
    const float* W;
    float* outp;
    if (blockIdx.y == 0)      { W = Wq; outp = g_q; }
    else if (blockIdx.y == 1) { W = Wk; outp = g_k; }
    else                      { W = Wv; outp = g_v; }

    const int tid = threadIdx.x;
    const int tx  = tid & 15;   // col group: cols tx*4 .. tx*4+3
    const int ty  = tid >> 4;   // row group: rows ty*8 .. ty*8+7

    unsigned long long acc[4][4];   // row-pairs (2i,2i+1) x 4 cols
    #pragma unroll
    for (int i = 0; i < 4; i++)
        #pragma unroll
        for (int j = 0; j < 4; j++) acc[i][j] = 0ULL;

    for (int k0 = 0; k0 < DMODEL; k0 += 32) {
        __syncthreads();
        // load x chunk transposed: 128 rows x 32 k (16 floats per thread)
        {
            const int row = tid >> 1;
            const int seg = (tid & 1) * 16;
            const float* src = x + (size_t)(rt0 + row) * DMODEL + k0 + seg;
            #pragma unroll
            for (int u = 0; u < 4; u++) {
                float4 v = *(const float4*)(src + u * 4);
                xsT[seg + u*4 + 0][row] = v.x;
                xsT[seg + u*4 + 1][row] = v.y;
                xsT[seg + u*4 + 2][row] = v.z;
                xsT[seg + u*4 + 3][row] = v.w;
            }
        }
        // load W chunk: 32 x 64 (8 floats per thread)
        {
            const int idx = tid * 8;
            const int r = idx >> 6;
            const int c = idx & 63;
            const float* wsrc = W + (size_t)(k0 + r) * HSZ + c;
            float4 w0 = *(const float4*)(wsrc);
            float4 w1 = *(const float4*)(wsrc + 4);
            *(float4*)&ws[r][c]     = w0;
            *(float4*)&ws[r][c + 4] = w1;
        }
        __syncthreads();

        #pragma unroll 8
        for (int kk = 0; kk < 32; kk++) {
            const ulonglong2* ap = (const ulonglong2*)&xsT[kk][ty * 8];
            ulonglong2 aA = ap[0], aB = ap[1];
            unsigned long long a2[4] = { aA.x, aA.y, aB.x, aB.y };  // row pairs
            float4 bq = *(const float4*)&ws[kk][tx * 4];
            unsigned long long b2[4] = { pk2(bq.x, bq.x), pk2(bq.y, bq.y),
                                         pk2(bq.z, bq.z), pk2(bq.w, bq.w) };
            #pragma unroll
            for (int i = 0; i < 4; i++)
                #pragma unroll
                for (int j = 0; j < 4; j++)
                    acc[i][j] = fma2(a2[i], b2[j], acc[i][j]);
        }
    }

    #pragma unroll
    for (int i = 0; i < 4; i++) {
        const int r0 = rt0 + ty * 8 + 2 * i;
        #pragma unroll
        for (int j = 0; j < 4; j++) {
            float2 v = up2(acc[i][j]);
            outp[(size_t)r0       * HSZ + tx * 4 + j] = v.x;
            outp[(size_t)(r0 + 1) * HSZ + tx * 4 + j] = v.y;
        }
    }
}

// ============================================================================
// Flash attention: per (128-query tile, batch). 256 threads: thread pair
// (2r, 2r+1) owns query row r; half=0 takes j/d 0..31, half=1 takes 32..63.
// Online softmax; all dot products via fp32x2 FMA.
// ============================================================================
struct AttnSmem {
    float Ks[64][68];   // pad 68: 16B-aligned rows, +4 bank shift per row
    float Vs[64][68];
    float Ss[128][65];  // per-row logits
};

__global__ __launch_bounds__(256, 1) void attn_kernel(float* __restrict__ outp)
{
    extern __shared__ char smem_raw[];
    AttnSmem* sm = (AttnSmem*)smem_raw;

    const int bb   = blockIdx.y;
    const int q0   = blockIdx.x * 128;
    const int tid  = threadIdx.x;
    const int row  = tid >> 1;
    const int half = tid & 1;
    const float scale = 0.03125f;   // D^-0.5 = 1/32 exactly

    // q row, pre-scaled, packed as 32 x f32x2
    unsigned long long q2[32];
    {
        const float* qp = g_q + ((size_t)bb * SEQ + q0 + row) * HSZ;
        #pragma unroll
        for (int u = 0; u < 16; u++) {
            float4 v = *(const float4*)(qp + u * 4);
            q2[2*u]     = pk2(v.x * scale, v.y * scale);
            q2[2*u + 1] = pk2(v.z * scale, v.w * scale);
        }
    }
    unsigned long long o2[16];      // this thread's 32 output dims
    #pragma unroll
    for (int i = 0; i < 16; i++) o2[i] = 0ULL;
    float m = -1e30f, l = 0.0f;

    const float* kb = g_k + (size_t)bb * SEQ * HSZ;
    const float* vb = g_v + (size_t)bb * SEQ * HSZ;
    const int lr = tid >> 2;          // load row 0..63
    const int lc = (tid & 3) * 16;    // load col seg

    for (int kt = 0; kt < SEQ; kt += 64) {
        __syncthreads();
        {
            const float* ksrc = kb + (size_t)(kt + lr) * HSZ + lc;
            const float* vsrc = vb + (size_t)(kt + lr) * HSZ + lc;
            #pragma unroll
            for (int u = 0; u < 4; u++) {
                *(float4*)&sm->Ks[lr][lc + u*4] = *(const float4*)(ksrc + u*4);
                *(float4*)&sm->Vs[lr][lc + u*4] = *(const float4*)(vsrc + u*4);
            }
        }
        __syncthreads();

        // ---- S = q . K^T for this thread's 32 keys (j = 2*jj + half:
        //      interleaved so the pair's two LDS addresses land on different banks)
        float tmax = -1e30f;
        #pragma unroll 4
        for (int jj = 0; jj < 32; jj++) {
            const int j = 2 * jj + half;
            const ulonglong2* kp = (const ulonglong2*)&sm->Ks[j][0];
            unsigned long long acc0 = 0ULL, acc1 = 0ULL;
            #pragma unroll
            for (int i4 = 0; i4 < 16; i4++) {
                ulonglong2 kv = kp[i4];
                acc0 = fma2(q2[2*i4],     kv.x, acc0);
                acc1 = fma2(q2[2*i4 + 1], kv.y, acc1);
            }
            float2 pa = up2(acc0), pb = up2(acc1);
            float s = (pa.x + pb.x) + (pa.y + pb.y);
            tmax = fmaxf(tmax, s);
            sm->Ss[row][j] = s;
        }
        __syncwarp();
        tmax = fmaxf(tmax, __shfl_xor_sync(0xFFFFFFFFu, tmax, 1));

        const float m_new = fmaxf(m, tmax);
        const float corr  = __expf(m - m_new);
        m = m_new;
        l *= corr;
        const unsigned long long corr2 = pk2(corr, corr);
        #pragma unroll
        for (int i = 0; i < 16; i++) o2[i] = mul2(o2[i], corr2);

        // ---- O += P . V over all 64 keys, this thread's 32-dim half of V.
        //      Both pair threads accumulate the full l (no final combine needed).
        const int db = half * 32;
        #pragma unroll 2
        for (int j = 0; j < 64; j++) {
            const float p = __expf(sm->Ss[row][j] - m_new);
            l += p;
            const unsigned long long p2v = pk2(p, p);
            const ulonglong2* vp = (const ulonglong2*)&sm->Vs[j][db];
            #pragma unroll
            for (int i4 = 0; i4 < 8; i4++) {
                ulonglong2 vv = vp[i4];
                o2[2*i4]     = fma2(p2v, vv.x, o2[2*i4]);
                o2[2*i4 + 1] = fma2(p2v, vv.y, o2[2*i4 + 1]);
            }
        }
    }

    const float inv = 1.0f / l;
    float* op = outp + ((size_t)bb * SEQ + q0 + row) * HSZ + half * 32;
    #pragma unroll
    for (int i4 = 0; i4 < 8; i4++) {
        float2 v0 = up2(o2[2*i4]);
        float2 v1 = up2(o2[2*i4 + 1]);
        float4 w;
        w.x = v0.x * inv; w.y = v0.y * inv;
        w.z = v1.x * inv; w.w = v1.y * inv;
        *(float4*)(op + i4 * 4) = w;
    }
}

// ============================================================================
extern "C" void kernel_launch(void* const* d_in, const int* in_sizes, int n_in,
                              void* d_out, int out_size)
{
    (void)in_sizes; (void)n_in; (void)out_size;
    const float* x  = (const float*)d_in[0];
    const float* Wq = (const float*)d_in[1];
    const float* Wk = (const float*)d_in[2];
    const float* Wv = (const float*)d_in[3];
    float* out = (float*)d_out;

    dim3 gp(NROWS / 128, 3);
    proj_kernel<<<gp, 256>>>(x, Wq, Wk, Wv);

    const size_t shmem = sizeof(AttnSmem);   // ~66.5 KB -> needs opt-in
    cudaFuncSetAttribute(attn_kernel,
                         cudaFuncAttributeMaxDynamicSharedMemorySize, (int)shmem);
    dim3 ga(SEQ / 128, BATCH);
    attn_kernel<<<ga, 256, shmem>>>(out);
}

// round 3
// speedup vs baseline: 3.2366x; 3.2366x over previous
#include <cuda_runtime.h>
#include <cstdint>

#define BATCH  4
#define SEQ    4096
#define DMODEL 1024
#define HSZ    64
#define NROWS  (BATCH*SEQ)

// Scratch for projected Q/K/V (device globals: no allocation allowed)
__device__ float g_q[NROWS*HSZ];   // [b][t][h]
__device__ float g_k[NROWS*HSZ];   // [b][t][h]
__device__ float g_v[NROWS*HSZ];   // [b][t][h]

// ============================ helpers =======================================
static __device__ __forceinline__ unsigned f2tf(float f){
    unsigned r; asm("cvt.rna.tf32.f32 %0, %1;" : "=r"(r) : "f"(f)); return r;
}
static __device__ __forceinline__ float ex2f(float x){
    float y; asm("ex2.approx.f32 %0, %1;" : "=f"(y) : "f"(x)); return y;
}
static __device__ __forceinline__ void mma8(float c[4], const unsigned a[4],
                                            unsigned b0, unsigned b1){
    asm("mma.sync.aligned.m16n8k8.row.col.f32.tf32.tf32.f32 "
        "{%0,%1,%2,%3}, {%4,%5,%6,%7}, {%8,%9}, {%0,%1,%2,%3};"
        : "+f"(c[0]), "+f"(c[1]), "+f"(c[2]), "+f"(c[3])
        : "r"(a[0]), "r"(a[1]), "r"(a[2]), "r"(a[3]), "r"(b0), "r"(b1));
}

// packed fp32x2 (projection kernel)
static __device__ __forceinline__ unsigned long long pk2(float lo, float hi){
    unsigned long long r; asm("mov.b64 %0, {%1,%2};" : "=l"(r) : "f"(lo), "f"(hi)); return r;
}
static __device__ __forceinline__ float2 up2(unsigned long long v){
    float2 f; asm("mov.b64 {%0,%1}, %2;" : "=f"(f.x), "=f"(f.y) : "l"(v)); return f;
}
static __device__ __forceinline__ unsigned long long fma2(unsigned long long a,
                                                          unsigned long long b,
                                                          unsigned long long c){
    unsigned long long d;
    asm("fma.rn.f32x2 %0, %1, %2, %3;" : "=l"(d) : "l"(a), "l"(b), "l"(c));
    return d;
}

// ============================================================================
// Projection: out[n, h] = sum_d x[n, d] * W[d, h]   (plain layout for q/k/v)
// ============================================================================
__global__ __launch_bounds__(256, 1) void proj_kernel(
    const float* __restrict__ x, const float* __restrict__ Wq,
    const float* __restrict__ Wk, const float* __restrict__ Wv)
{
    __shared__ float xsT[32][132];
    __shared__ float ws[32][64];

    const int rt0 = blockIdx.x * 128;
    const float* W;
    float* outp;
    if (blockIdx.y == 0)      { W = Wq; outp = g_q; }
    else if (blockIdx.y == 1) { W = Wk; outp = g_k; }
    else                      { W = Wv; outp = g_v; }

    const int tid = threadIdx.x;
    const int tx  = tid & 15;
    const int ty  = tid >> 4;

    unsigned long long acc[4][4];
    #pragma unroll
    for (int i = 0; i < 4; i++)
        #pragma unroll
        for (int j = 0; j < 4; j++) acc[i][j] = 0ULL;

    for (int k0 = 0; k0 < DMODEL; k0 += 32) {
        __syncthreads();
        {
            const int row = tid >> 1;
            const int seg = (tid & 1) * 16;
            const float* src = x + (size_t)(rt0 + row) * DMODEL + k0 + seg;
            #pragma unroll
            for (int u = 0; u < 4; u++) {
                float4 v = *(const float4*)(src + u * 4);
                xsT[seg + u*4 + 0][row] = v.x;
                xsT[seg + u*4 + 1][row] = v.y;
                xsT[seg + u*4 + 2][row] = v.z;
                xsT[seg + u*4 + 3][row] = v.w;
            }
        }
        {
            const int idx = tid * 8;
            const int r = idx >> 6;
            const int c = idx & 63;
            const float* wsrc = W + (size_t)(k0 + r) * HSZ + c;
            *(float4*)&ws[r][c]     = *(const float4*)(wsrc);
            *(float4*)&ws[r][c + 4] = *(const float4*)(wsrc + 4);
        }
        __syncthreads();

        #pragma unroll 8
        for (int kk = 0; kk < 32; kk++) {
            const ulonglong2* ap = (const ulonglong2*)&xsT[kk][ty * 8];
            ulonglong2 aA = ap[0], aB = ap[1];
            unsigned long long a2[4] = { aA.x, aA.y, aB.x, aB.y };
            float4 bq = *(const float4*)&ws[kk][tx * 4];
            unsigned long long b2[4] = { pk2(bq.x, bq.x), pk2(bq.y, bq.y),
                                         pk2(bq.z, bq.z), pk2(bq.w, bq.w) };
            #pragma unroll
            for (int i = 0; i < 4; i++)
                #pragma unroll
                for (int j = 0; j < 4; j++)
                    acc[i][j] = fma2(a2[i], b2[j], acc[i][j]);
        }
    }

    #pragma unroll
    for (int i = 0; i < 4; i++) {
        const int r0 = rt0 + ty * 8 + 2 * i;
        #pragma unroll
        for (int j = 0; j < 4; j++) {
            float2 v = up2(acc[i][j]);
            outp[(size_t)r0       * HSZ + tx * 4 + j] = v.x;
            outp[(size_t)(r0 + 1) * HSZ + tx * 4 + j] = v.y;
        }
    }
}

// ============================================================================
// mma.sync tf32 flash attention.
// CTA: (128-query tile, batch). 8 warps in a 4(M) x 2(N) grid:
//   warp (mw, nw): queries mw*32..+31, keys nw*64..+63 of each 128-key tile.
// Q fragments persistent in registers; P converted C-frag -> A-frag via shfl;
// per-key-half partial O/l combined through smem at the end.
// ============================================================================
#define KS_STRIDE 68   /* banks 4g+tg : bijective */
#define VS_STRIDE 72   /* banks 8tg+g : bijective */
#define KS_FLOATS (128*KS_STRIDE)
#define VS_FLOATS (128*VS_STRIDE)
#define ATTN_SMEM ((KS_FLOATS + VS_FLOATS) * 4)
#define OP_STRIDE 66

__global__ __launch_bounds__(256, 1) void attn_kernel(float* __restrict__ outp)
{
    extern __shared__ float smf[];
    unsigned* Ks = (unsigned*)smf;              // tf32 bits
    unsigned* Vs = (unsigned*)(smf + KS_FLOATS);

    const int tid  = threadIdx.x;
    const int lane = tid & 31;
    const int wid  = tid >> 5;
    const int mw   = wid & 3;         // M block (queries)
    const int nw   = wid >> 2;        // key half
    const int g    = lane >> 2;       // groupID
    const int tg   = lane & 3;        // threadID_in_group
    const int base = lane & 28;       // g*4 (quad base lane)
    const int b    = blockIdx.y;
    const int q0   = blockIdx.x * 128;

    const float qs = 1.4426950408889634f / 32.0f;  // log2(e) * D^-0.5

    // ---- persistent Q A-fragments: qa[mi][kt][4] ----
    unsigned qa[2][8][4];
    {
        const float* qb = g_q + ((size_t)b * SEQ + q0) * HSZ;
        #pragma unroll
        for (int mi = 0; mi < 2; mi++) {
            const int r0 = mw * 32 + mi * 16 + g;
            #pragma unroll
            for (int kt = 0; kt < 8; kt++) {
                const int c0 = kt * 8 + tg;
                qa[mi][kt][0] = f2tf(qb[(size_t)r0       * HSZ + c0]     * qs);
                qa[mi][kt][1] = f2tf(qb[(size_t)(r0 + 8) * HSZ + c0]     * qs);
                qa[mi][kt][2] = f2tf(qb[(size_t)r0       * HSZ + c0 + 4] * qs);
                qa[mi][kt][3] = f2tf(qb[(size_t)(r0 + 8) * HSZ + c0 + 4] * qs);
            }
        }
    }

    float o[2][8][4];
    #pragma unroll
    for (int mi = 0; mi < 2; mi++)
        #pragma unroll
        for (int nt = 0; nt < 8; nt++)
            #pragma unroll
            for (int j = 0; j < 4; j++) o[mi][nt][j] = 0.0f;
    float lsum[2][2] = {{0.0f, 0.0f}, {0.0f, 0.0f}};

    const float* kb = g_k + (size_t)b * SEQ * HSZ;
    const float* vb = g_v + (size_t)b * SEQ * HSZ;

    for (int it = 0; it < 32; it++) {
        __syncthreads();
        // ---- K/V tile -> smem (tf32-converted), coalesced gmem reads ----
        #pragma unroll
        for (int u = 0; u < 8; u++) {
            const int idx = u * 256 + tid;
            const int key = idx >> 4;
            const int h4  = (idx & 15) << 2;
            const size_t go = (size_t)(it * 128 + key) * HSZ + h4;
            float4 kv = *(const float4*)(kb + go);
            float4 vv = *(const float4*)(vb + go);
            uint4 kc = { f2tf(kv.x), f2tf(kv.y), f2tf(kv.z), f2tf(kv.w) };
            uint4 vc = { f2tf(vv.x), f2tf(vv.y), f2tf(vv.z), f2tf(vv.w) };
            *(uint4*)&Ks[key * KS_STRIDE + h4] = kc;
            *(uint4*)&Vs[key * VS_STRIDE + h4] = vc;
        }
        __syncthreads();

        // ---- S = Q . K^T : per warp 32 x 64 block ----
        float cs[2][8][4];
        #pragma unroll
        for (int nt = 0; nt < 8; nt++) {
            #pragma unroll
            for (int mi = 0; mi < 2; mi++)
                #pragma unroll
                for (int j = 0; j < 4; j++) cs[mi][nt][j] = 0.0f;
            const unsigned* krow = Ks + (nw * 64 + nt * 8 + g) * KS_STRIDE;
            #pragma unroll
            for (int kt = 0; kt < 8; kt++) {
                unsigned b0 = krow[kt * 8 + tg];
                unsigned b1 = krow[kt * 8 + tg + 4];
                mma8(cs[0][nt], qa[0][kt], b0, b1);
                mma8(cs[1][nt], qa[1][kt], b0, b1);
            }
        }

        // ---- softmax (max=0): p = exp2(s); tf32-round in place; row sums ----
        #pragma unroll
        for (int mi = 0; mi < 2; mi++)
            #pragma unroll
            for (int nt = 0; nt < 8; nt++) {
                #pragma unroll
                for (int j = 0; j < 4; j++) {
                    unsigned pb = f2tf(ex2f(cs[mi][nt][j]));
                    float pv = __uint_as_float(pb);
                    cs[mi][nt][j] = pv;
                    lsum[mi][j >> 1] += pv;
                }
            }

        // ---- O += P . V : A-frags from cs via shfl, B-frags from Vs ----
        #pragma unroll
        for (int kt = 0; kt < 8; kt++) {
            unsigned pa[2][4];
            #pragma unroll
            for (int mi = 0; mi < 2; mi++) {
                const int s0 = base + (tg >> 1);
                float w0 = __shfl_sync(0xFFFFFFFFu, cs[mi][kt][0], s0);
                float w1 = __shfl_sync(0xFFFFFFFFu, cs[mi][kt][1], s0);
                float w2 = __shfl_sync(0xFFFFFFFFu, cs[mi][kt][2], s0);
                float w3 = __shfl_sync(0xFFFFFFFFu, cs[mi][kt][3], s0);
                float w4 = __shfl_sync(0xFFFFFFFFu, cs[mi][kt][0], s0 + 2);
                float w5 = __shfl_sync(0xFFFFFFFFu, cs[mi][kt][1], s0 + 2);
                float w6 = __shfl_sync(0xFFFFFFFFu, cs[mi][kt][2], s0 + 2);
                float w7 = __shfl_sync(0xFFFFFFFFu, cs[mi][kt][3], s0 + 2);
                pa[mi][0] = __float_as_uint((tg & 1) ? w1 : w0);
                pa[mi][1] = __float_as_uint((tg & 1) ? w3 : w2);
                pa[mi][2] = __float_as_uint((tg & 1) ? w5 : w4);
                pa[mi][3] = __float_as_uint((tg & 1) ? w7 : w6);
            }
            const unsigned* vr0 = Vs + (nw * 64 + kt * 8 + tg)     * VS_STRIDE;
            const unsigned* vr1 = Vs + (nw * 64 + kt * 8 + tg + 4) * VS_STRIDE;
            #pragma unroll
            for (int nt = 0; nt < 8; nt++) {
                unsigned b0 = vr0[nt * 8 + g];
                unsigned b1 = vr1[nt * 8 + g];
                mma8(o[0][nt], pa[0], b0, b1);
                mma8(o[1][nt], pa[1], b0, b1);
            }
        }
    }

    // ---- reduce l within quads ----
    #pragma unroll
    for (int mi = 0; mi < 2; mi++)
        #pragma unroll
        for (int r = 0; r < 2; r++) {
            float v = lsum[mi][r];
            v += __shfl_xor_sync(0xFFFFFFFFu, v, 1);
            v += __shfl_xor_sync(0xFFFFFFFFu, v, 2);
            lsum[mi][r] = v;
        }

    // ---- combine key halves through smem (reuse Ks/Vs region) ----
    __syncthreads();
    float* Opart = smf;                       // [128][OP_STRIDE]
    float* lpart = smf + 128 * OP_STRIDE;     // [128]
    if (nw == 1) {
        #pragma unroll
        for (int mi = 0; mi < 2; mi++) {
            const int r0 = mw * 32 + mi * 16 + g;
            #pragma unroll
            for (int nt = 0; nt < 8; nt++) {
                const int c = nt * 8 + 2 * tg;
                *(float2*)&Opart[r0       * OP_STRIDE + c] = make_float2(o[mi][nt][0], o[mi][nt][1]);
                *(float2*)&Opart[(r0 + 8) * OP_STRIDE + c] = make_float2(o[mi][nt][2], o[mi][nt][3]);
            }
            if (tg == 0) {
                lpart[r0]     = lsum[mi][0];
                lpart[r0 + 8] = lsum[mi][1];
            }
        }
    }
    __syncthreads();
    if (nw == 0) {
        #pragma unroll
        for (int mi = 0; mi < 2; mi++) {
            const int r0 = mw * 32 + mi * 16 + g;
            const float inv0 = 1.0f / (lsum[mi][0] + lpart[r0]);
            const float inv1 = 1.0f / (lsum[mi][1] + lpart[r0 + 8]);
            float* ob0 = outp + ((size_t)b * SEQ + q0 + r0) * HSZ;
            float* ob1 = ob0 + 8 * HSZ;
            #pragma unroll
            for (int nt = 0; nt < 8; nt++) {
                const int c = nt * 8 + 2 * tg;
                float2 p0 = *(const float2*)&Opart[r0       * OP_STRIDE + c];
                float2 p1 = *(const float2*)&Opart[(r0 + 8) * OP_STRIDE + c];
                *(float2*)(ob0 + c) = make_float2((o[mi][nt][0] + p0.x) * inv0,
                                                  (o[mi][nt][1] + p0.y) * inv0);
                *(float2*)(ob1 + c) = make_float2((o[mi][nt][2] + p1.x) * inv1,
                                                  (o[mi][nt][3] + p1.y) * inv1);
            }
        }
    }
}

// ============================================================================
extern "C" void kernel_launch(void* const* d_in, const int* in_sizes, int n_in,
                              void* d_out, int out_size)
{
    (void)in_sizes; (void)n_in; (void)out_size;
    const float* x  = (const float*)d_in[0];
    const float* Wq = (const float*)d_in[1];
    const float* Wk = (const float*)d_in[2];
    const float* Wv = (const float*)d_in[3];
    float* out = (float*)d_out;

    dim3 gp(NROWS / 128, 3);
    proj_kernel<<<gp, 256>>>(x, Wq, Wk, Wv);

    cudaFuncSetAttribute(attn_kernel,
                         cudaFuncAttributeMaxDynamicSharedMemorySize, ATTN_SMEM);
    dim3 ga(SEQ / 128, BATCH);
    attn_kernel<<<ga, 256, ATTN_SMEM>>>(out);
}

// round 4
// speedup vs baseline: 3.6806x; 1.1372x over previous
#include <cuda_runtime.h>
#include <cstdint>

#define BATCH  4
#define SEQ    4096
#define DMODEL 1024
#define HSZ    64
#define NROWS  (BATCH*SEQ)

// Scratch for projected Q/K/V (device globals: no allocation allowed)
__device__ float g_q[NROWS*HSZ];   // [b][t][h]
__device__ float g_k[NROWS*HSZ];   // [b][t][h]
__device__ float g_v[NROWS*HSZ];   // [b][t][h]

// ============================ helpers =======================================
static __device__ __forceinline__ unsigned f2tf(float f){
    unsigned r; asm("cvt.rna.tf32.f32 %0, %1;" : "=r"(r) : "f"(f)); return r;
}
static __device__ __forceinline__ float ex2f(float x){
    float y; asm("ex2.approx.f32 %0, %1;" : "=f"(y) : "f"(x)); return y;
}
static __device__ __forceinline__ void mma8(float c[4], const unsigned a[4],
                                            unsigned b0, unsigned b1){
    asm("mma.sync.aligned.m16n8k8.row.col.f32.tf32.tf32.f32 "
        "{%0,%1,%2,%3}, {%4,%5,%6,%7}, {%8,%9}, {%0,%1,%2,%3};"
        : "+f"(c[0]), "+f"(c[1]), "+f"(c[2]), "+f"(c[3])
        : "r"(a[0]), "r"(a[1]), "r"(a[2]), "r"(a[3]), "r"(b0), "r"(b1));
}

// ============================================================================
// Fused tensor-core projection: Q/K/V = x @ {Wq,Wk,Wv} in one pass over x.
// Grid 128 CTAs (128 rows each), 256 threads = 8 warps: 4(M: 32-row stripes)
// x 2(N: halves of the 24 8-col output tiles  [3 matrices x 8 tiles]).
// K-chunks of 64 over D=1024; x and W staged in smem as tf32.
// ============================================================================
#define PX_STRIDE 68   /* banks 4g+tg bijective */
#define PW_STRIDE 72   /* banks 8tg+g bijective */
#define PROJ_SMEM ((128*PX_STRIDE + 3*64*PW_STRIDE) * 4)

__global__ __launch_bounds__(256, 1) void proj_kernel(
    const float* __restrict__ x, const float* __restrict__ Wq,
    const float* __restrict__ Wk, const float* __restrict__ Wv)
{
    extern __shared__ unsigned ps[];
    unsigned* Xs = ps;                       // [128][PX_STRIDE] tf32
    unsigned* Ws = ps + 128 * PX_STRIDE;     // [3][64][PW_STRIDE] tf32

    const int tid  = threadIdx.x;
    const int lane = tid & 31;
    const int wid  = tid >> 5;
    const int mw   = wid & 3;        // 32-row stripe
    const int nw   = wid >> 2;       // which 12 of the 24 output tiles
    const int g    = lane >> 2;
    const int tg   = lane & 3;
    const int rt0  = blockIdx.x * 128;

    float c[2][12][4];
    #pragma unroll
    for (int mi = 0; mi < 2; mi++)
        #pragma unroll
        for (int t = 0; t < 12; t++)
            #pragma unroll
            for (int j = 0; j < 4; j++) c[mi][t][j] = 0.0f;

    for (int k0 = 0; k0 < DMODEL; k0 += 64) {
        __syncthreads();
        // x chunk [128 x 64] -> tf32 smem
        #pragma unroll
        for (int u = 0; u < 8; u++) {
            const int idx = u * 256 + tid;
            const int row = idx >> 4, c4 = (idx & 15) * 4;
            float4 v = *(const float4*)(x + (size_t)(rt0 + row) * DMODEL + k0 + c4);
            uint4 t4 = { f2tf(v.x), f2tf(v.y), f2tf(v.z), f2tf(v.w) };
            *(uint4*)&Xs[row * PX_STRIDE + c4] = t4;
        }
        // W chunks [64 x 64] x3 -> tf32 smem
        #pragma unroll
        for (int w = 0; w < 3; w++) {
            const float* Wp = (w == 0) ? Wq : (w == 1) ? Wk : Wv;
            #pragma unroll
            for (int u = 0; u < 4; u++) {
                const int idx = u * 256 + tid;
                const int row = idx >> 4, c4 = (idx & 15) * 4;
                float4 v = *(const float4*)(Wp + (size_t)(k0 + row) * HSZ + c4);
                uint4 t4 = { f2tf(v.x), f2tf(v.y), f2tf(v.z), f2tf(v.w) };
                *(uint4*)&Ws[w * 64 * PW_STRIDE + row * PW_STRIDE + c4] = t4;
            }
        }
        __syncthreads();

        // A fragments for this warp's 32 rows
        unsigned a[2][8][4];
        #pragma unroll
        for (int mi = 0; mi < 2; mi++) {
            const int r0 = mw * 32 + mi * 16 + g;
            #pragma unroll
            for (int kt = 0; kt < 8; kt++) {
                const int cb = kt * 8 + tg;
                a[mi][kt][0] = Xs[r0       * PX_STRIDE + cb];
                a[mi][kt][1] = Xs[(r0 + 8) * PX_STRIDE + cb];
                a[mi][kt][2] = Xs[r0       * PX_STRIDE + cb + 4];
                a[mi][kt][3] = Xs[(r0 + 8) * PX_STRIDE + cb + 4];
            }
        }
        #pragma unroll
        for (int t = 0; t < 12; t++) {
            const int gt = nw * 12 + t;
            const unsigned* wb = Ws + (gt >> 3) * 64 * PW_STRIDE + (gt & 7) * 8 + g;
            #pragma unroll
            for (int kt = 0; kt < 8; kt++) {
                unsigned b0 = wb[(kt * 8 + tg)     * PW_STRIDE];
                unsigned b1 = wb[(kt * 8 + tg + 4) * PW_STRIDE];
                mma8(c[0][t], a[0][kt], b0, b1);
                mma8(c[1][t], a[1][kt], b0, b1);
            }
        }
    }

    // epilogue: scatter C fragments to g_q/g_k/g_v
    #pragma unroll
    for (int t = 0; t < 12; t++) {
        const int gt = nw * 12 + t;
        const int w  = gt >> 3;
        const int h0 = (gt & 7) * 8 + 2 * tg;
        float* outp = (w == 0) ? g_q : (w == 1) ? g_k : g_v;
        #pragma unroll
        for (int mi = 0; mi < 2; mi++) {
            const int r = rt0 + mw * 32 + mi * 16 + g;
            *(float2*)&outp[(size_t)r       * HSZ + h0] = make_float2(c[mi][t][0], c[mi][t][1]);
            *(float2*)&outp[(size_t)(r + 8) * HSZ + h0] = make_float2(c[mi][t][2], c[mi][t][3]);
        }
    }
}

// ============================================================================
// mma.sync tf32 flash attention, 512 threads = 16 warps: 4(M: 32 queries) x
// 4(N: 32-key quarters of each 128-key tile). Q frags persistent; P via shfl;
// 3-round smem combine of the 4 key-quarter partials.
// ============================================================================
#define KS_STRIDE 68
#define VS_STRIDE 72
#define KS_FLOATS (128*KS_STRIDE)
#define VS_FLOATS (128*VS_STRIDE)
#define ATTN_SMEM ((KS_FLOATS + VS_FLOATS) * 4)
#define OP_STRIDE 66

__global__ __launch_bounds__(512, 1) void attn_kernel(float* __restrict__ outp)
{
    extern __shared__ float smf[];
    unsigned* Ks = (unsigned*)smf;
    unsigned* Vs = (unsigned*)(smf + KS_FLOATS);

    const int tid  = threadIdx.x;
    const int lane = tid & 31;
    const int wid  = tid >> 5;
    const int mw   = wid & 3;        // query block (32 rows)
    const int nw   = wid >> 2;       // key quarter (32 keys)
    const int g    = lane >> 2;
    const int tg   = lane & 3;
    const int base = lane & 28;
    const int b    = blockIdx.y;
    const int q0   = blockIdx.x * 128;

    const float qs = 1.4426950408889634f / 32.0f;  // log2(e) * D^-0.5

    // persistent Q A-fragments
    unsigned qa[2][8][4];
    {
        const float* qb = g_q + ((size_t)b * SEQ + q0) * HSZ;
        #pragma unroll
        for (int mi = 0; mi < 2; mi++) {
            const int r0 = mw * 32 + mi * 16 + g;
            #pragma unroll
            for (int kt = 0; kt < 8; kt++) {
                const int c0 = kt * 8 + tg;
                qa[mi][kt][0] = f2tf(qb[(size_t)r0       * HSZ + c0]     * qs);
                qa[mi][kt][1] = f2tf(qb[(size_t)(r0 + 8) * HSZ + c0]     * qs);
                qa[mi][kt][2] = f2tf(qb[(size_t)r0       * HSZ + c0 + 4] * qs);
                qa[mi][kt][3] = f2tf(qb[(size_t)(r0 + 8) * HSZ + c0 + 4] * qs);
            }
        }
    }

    float o[2][8][4];
    #pragma unroll
    for (int mi = 0; mi < 2; mi++)
        #pragma unroll
        for (int nt = 0; nt < 8; nt++)
            #pragma unroll
            for (int j = 0; j < 4; j++) o[mi][nt][j] = 0.0f;
    float lsum[2][2] = {{0.0f, 0.0f}, {0.0f, 0.0f}};

    const float* kb = g_k + (size_t)b * SEQ * HSZ;
    const float* vb = g_v + (size_t)b * SEQ * HSZ;

    for (int it = 0; it < 32; it++) {
        __syncthreads();
        // K/V tile [128 x 64] -> tf32 smem
        #pragma unroll
        for (int u = 0; u < 4; u++) {
            const int idx = u * 512 + tid;
            const int key = idx >> 4;
            const int h4  = (idx & 15) << 2;
            const size_t go = (size_t)(it * 128 + key) * HSZ + h4;
            float4 kv = *(const float4*)(kb + go);
            float4 vv = *(const float4*)(vb + go);
            uint4 kc = { f2tf(kv.x), f2tf(kv.y), f2tf(kv.z), f2tf(kv.w) };
            uint4 vc = { f2tf(vv.x), f2tf(vv.y), f2tf(vv.z), f2tf(vv.w) };
            *(uint4*)&Ks[key * KS_STRIDE + h4] = kc;
            *(uint4*)&Vs[key * VS_STRIDE + h4] = vc;
        }
        __syncthreads();

        // S = Q . K^T : this warp's 32 queries x 32 keys
        float cs[2][4][4];
        #pragma unroll
        for (int nt = 0; nt < 4; nt++) {
            #pragma unroll
            for (int mi = 0; mi < 2; mi++)
                #pragma unroll
                for (int j = 0; j < 4; j++) cs[mi][nt][j] = 0.0f;
            const unsigned* krow = Ks + (nw * 32 + nt * 8 + g) * KS_STRIDE;
            #pragma unroll
            for (int kt = 0; kt < 8; kt++) {
                unsigned b0 = krow[kt * 8 + tg];
                unsigned b1 = krow[kt * 8 + tg + 4];
                mma8(cs[0][nt], qa[0][kt], b0, b1);
                mma8(cs[1][nt], qa[1][kt], b0, b1);
            }
        }

        // softmax (max=0): p = exp2(s), tf32-round, row sums
        #pragma unroll
        for (int mi = 0; mi < 2; mi++)
            #pragma unroll
            for (int nt = 0; nt < 4; nt++)
                #pragma unroll
                for (int j = 0; j < 4; j++) {
                    unsigned pb = f2tf(ex2f(cs[mi][nt][j]));
                    float pv = __uint_as_float(pb);
                    cs[mi][nt][j] = pv;
                    lsum[mi][j >> 1] += pv;
                }

        // O += P . V : A-frags from cs via shfl, B-frags from Vs
        #pragma unroll
        for (int kt = 0; kt < 4; kt++) {
            unsigned pa[2][4];
            #pragma unroll
            for (int mi = 0; mi < 2; mi++) {
                const int s0 = base + (tg >> 1);
                float w0 = __shfl_sync(0xFFFFFFFFu, cs[mi][kt][0], s0);
                float w1 = __shfl_sync(0xFFFFFFFFu, cs[mi][kt][1], s0);
                float w2 = __shfl_sync(0xFFFFFFFFu, cs[mi][kt][2], s0);
                float w3 = __shfl_sync(0xFFFFFFFFu, cs[mi][kt][3], s0);
                float w4 = __shfl_sync(0xFFFFFFFFu, cs[mi][kt][0], s0 + 2);
                float w5 = __shfl_sync(0xFFFFFFFFu, cs[mi][kt][1], s0 + 2);
                float w6 = __shfl_sync(0xFFFFFFFFu, cs[mi][kt][2], s0 + 2);
                float w7 = __shfl_sync(0xFFFFFFFFu, cs[mi][kt][3], s0 + 2);
                pa[mi][0] = __float_as_uint((tg & 1) ? w1 : w0);
                pa[mi][1] = __float_as_uint((tg & 1) ? w3 : w2);
                pa[mi][2] = __float_as_uint((tg & 1) ? w5 : w4);
                pa[mi][3] = __float_as_uint((tg & 1) ? w7 : w6);
            }
            const unsigned* vr0 = Vs + (nw * 32 + kt * 8 + tg)     * VS_STRIDE;
            const unsigned* vr1 = Vs + (nw * 32 + kt * 8 + tg + 4) * VS_STRIDE;
            #pragma unroll
            for (int nt = 0; nt < 8; nt++) {
                unsigned b0 = vr0[nt * 8 + g];
                unsigned b1 = vr1[nt * 8 + g];
                mma8(o[0][nt], pa[0], b0, b1);
                mma8(o[1][nt], pa[1], b0, b1);
            }
        }
    }

    // reduce l within quads
    #pragma unroll
    for (int mi = 0; mi < 2; mi++)
        #pragma unroll
        for (int r = 0; r < 2; r++) {
            float v = lsum[mi][r];
            v += __shfl_xor_sync(0xFFFFFFFFu, v, 1);
            v += __shfl_xor_sync(0xFFFFFFFFu, v, 2);
            lsum[mi][r] = v;
        }

    // 3-round combine of key-quarter partials into nw==0 warps
    float* Opart = smf;
    float* lpart = smf + 128 * OP_STRIDE;
    for (int p = 1; p < 4; p++) {
        __syncthreads();
        if (nw == p) {
            #pragma unroll
            for (int mi = 0; mi < 2; mi++) {
                const int r0 = mw * 32 + mi * 16 + g;
                #pragma unroll
                for (int nt = 0; nt < 8; nt++) {
                    const int c = nt * 8 + 2 * tg;
                    *(float2*)&Opart[r0       * OP_STRIDE + c] = make_float2(o[mi][nt][0], o[mi][nt][1]);
                    *(float2*)&Opart[(r0 + 8) * OP_STRIDE + c] = make_float2(o[mi][nt][2], o[mi][nt][3]);
                }
                if (tg == 0) {
                    lpart[r0]     = lsum[mi][0];
                    lpart[r0 + 8] = lsum[mi][1];
                }
            }
        }
        __syncthreads();
        if (nw == 0) {
            #pragma unroll
            for (int mi = 0; mi < 2; mi++) {
                const int r0 = mw * 32 + mi * 16 + g;
                #pragma unroll
                for (int nt = 0; nt < 8; nt++) {
                    const int c = nt * 8 + 2 * tg;
                    float2 p0 = *(const float2*)&Opart[r0       * OP_STRIDE + c];
                    float2 p1 = *(const float2*)&Opart[(r0 + 8) * OP_STRIDE + c];
                    o[mi][nt][0] += p0.x; o[mi][nt][1] += p0.y;
                    o[mi][nt][2] += p1.x; o[mi][nt][3] += p1.y;
                }
                lsum[mi][0] += lpart[r0];
                lsum[mi][1] += lpart[r0 + 8];
            }
        }
    }

    if (nw == 0) {
        #pragma unroll
        for (int mi = 0; mi < 2; mi++) {
            const int r0 = mw * 32 + mi * 16 + g;
            const float inv0 = 1.0f / lsum[mi][0];
            const float inv1 = 1.0f / lsum[mi][1];
            float* ob0 = outp + ((size_t)b * SEQ + q0 + r0) * HSZ;
            float* ob1 = ob0 + 8 * HSZ;
            #pragma unroll
            for (int nt = 0; nt < 8; nt++) {
                const int c = nt * 8 + 2 * tg;
                *(float2*)(ob0 + c) = make_float2(o[mi][nt][0] * inv0, o[mi][nt][1] * inv0);
                *(float2*)(ob1 + c) = make_float2(o[mi][nt][2] * inv1, o[mi][nt][3] * inv1);
            }
        }
    }
}

// ============================================================================
extern "C" void kernel_launch(void* const* d_in, const int* in_sizes, int n_in,
                              void* d_out, int out_size)
{
    (void)in_sizes; (void)n_in; (void)out_size;
    const float* x  = (const float*)d_in[0];
    const float* Wq = (const float*)d_in[1];
    const float* Wk = (const float*)d_in[2];
    const float* Wv = (const float*)d_in[3];
    float* out = (float*)d_out;

    cudaFuncSetAttribute(proj_kernel,
                         cudaFuncAttributeMaxDynamicSharedMemorySize, PROJ_SMEM);
    proj_kernel<<<NROWS / 128, 256, PROJ_SMEM>>>(x, Wq, Wk, Wv);

    cudaFuncSetAttribute(attn_kernel,
                         cudaFuncAttributeMaxDynamicSharedMemorySize, ATTN_SMEM);
    dim3 ga(SEQ / 128, BATCH);
    attn_kernel<<<ga, 512, ATTN_SMEM>>>(out);
}

// round 5
// speedup vs baseline: 4.9579x; 1.3470x over previous
#include <cuda_runtime.h>
#include <cstdint>

#define BATCH  4
#define SEQ    4096
#define DMODEL 1024
#define HSZ    64
#define NROWS  (BATCH*SEQ)

// Scratch for projected Q/K/V (device globals: no allocation allowed)
__device__ float g_q[NROWS*HSZ];   // [b][t][h]
__device__ float g_k[NROWS*HSZ];   // [b][t][h]
__device__ float g_v[NROWS*HSZ];   // [b][t][h]

// ============================ helpers =======================================
static __device__ __forceinline__ unsigned f2tf(float f){
    unsigned r; asm("cvt.rna.tf32.f32 %0, %1;" : "=r"(r) : "f"(f)); return r;
}
static __device__ __forceinline__ float ex2f(float x){
    float y; asm("ex2.approx.f32 %0, %1;" : "=f"(y) : "f"(x)); return y;
}
static __device__ __forceinline__ void mma8(float c[4], const unsigned a[4],
                                            unsigned b0, unsigned b1){
    asm("mma.sync.aligned.m16n8k8.row.col.f32.tf32.tf32.f32 "
        "{%0,%1,%2,%3}, {%4,%5,%6,%7}, {%8,%9}, {%0,%1,%2,%3};"
        : "+f"(c[0]), "+f"(c[1]), "+f"(c[2]), "+f"(c[3])
        : "r"(a[0]), "r"(a[1]), "r"(a[2]), "r"(a[3]), "r"(b0), "r"(b1));
}
#define CP_ASYNC16(saddr, gaddr) \
    asm volatile("cp.async.cg.shared.global [%0], [%1], 16;" :: "r"(saddr), "l"(gaddr))
#define CP_COMMIT() asm volatile("cp.async.commit_group;" ::: "memory")
#define CP_WAIT0()  asm volatile("cp.async.wait_group 0;" ::: "memory")

// ============================================================================
// Fused tensor-core projection: Q/K/V = x @ {Wq,Wk,Wv} in one pass over x.
// Grid 128 CTAs (128 rows each), 256 threads = 8 warps: 4(M) x 2(N of 24 tiles)
// ============================================================================
#define PX_STRIDE 68
#define PW_STRIDE 72
#define PROJ_SMEM ((128*PX_STRIDE + 3*64*PW_STRIDE) * 4)

__global__ __launch_bounds__(256, 1) void proj_kernel(
    const float* __restrict__ x, const float* __restrict__ Wq,
    const float* __restrict__ Wk, const float* __restrict__ Wv)
{
    extern __shared__ unsigned ps[];
    unsigned* Xs = ps;                       // [128][PX_STRIDE] tf32
    unsigned* Ws = ps + 128 * PX_STRIDE;     // [3][64][PW_STRIDE] tf32

    const int tid  = threadIdx.x;
    const int lane = tid & 31;
    const int wid  = tid >> 5;
    const int mw   = wid & 3;
    const int nw   = wid >> 2;
    const int g    = lane >> 2;
    const int tg   = lane & 3;
    const int rt0  = blockIdx.x * 128;

    float c[2][12][4];
    #pragma unroll
    for (int mi = 0; mi < 2; mi++)
        #pragma unroll
        for (int t = 0; t < 12; t++)
            #pragma unroll
            for (int j = 0; j < 4; j++) c[mi][t][j] = 0.0f;

    for (int k0 = 0; k0 < DMODEL; k0 += 64) {
        __syncthreads();
        #pragma unroll
        for (int u = 0; u < 8; u++) {
            const int idx = u * 256 + tid;
            const int row = idx >> 4, c4 = (idx & 15) * 4;
            float4 v = *(const float4*)(x + (size_t)(rt0 + row) * DMODEL + k0 + c4);
            uint4 t4 = { f2tf(v.x), f2tf(v.y), f2tf(v.z), f2tf(v.w) };
            *(uint4*)&Xs[row * PX_STRIDE + c4] = t4;
        }
        #pragma unroll
        for (int w = 0; w < 3; w++) {
            const float* Wp = (w == 0) ? Wq : (w == 1) ? Wk : Wv;
            #pragma unroll
            for (int u = 0; u < 4; u++) {
                const int idx = u * 256 + tid;
                const int row = idx >> 4, c4 = (idx & 15) * 4;
                float4 v = *(const float4*)(Wp + (size_t)(k0 + row) * HSZ + c4);
                uint4 t4 = { f2tf(v.x), f2tf(v.y), f2tf(v.z), f2tf(v.w) };
                *(uint4*)&Ws[w * 64 * PW_STRIDE + row * PW_STRIDE + c4] = t4;
            }
        }
        __syncthreads();

        unsigned a[2][8][4];
        #pragma unroll
        for (int mi = 0; mi < 2; mi++) {
            const int r0 = mw * 32 + mi * 16 + g;
            #pragma unroll
            for (int kt = 0; kt < 8; kt++) {
                const int cb = kt * 8 + tg;
                a[mi][kt][0] = Xs[r0       * PX_STRIDE + cb];
                a[mi][kt][1] = Xs[(r0 + 8) * PX_STRIDE + cb];
                a[mi][kt][2] = Xs[r0       * PX_STRIDE + cb + 4];
                a[mi][kt][3] = Xs[(r0 + 8) * PX_STRIDE + cb + 4];
            }
        }
        #pragma unroll
        for (int t = 0; t < 12; t++) {
            const int gt = nw * 12 + t;
            const unsigned* wb = Ws + (gt >> 3) * 64 * PW_STRIDE + (gt & 7) * 8 + g;
            #pragma unroll
            for (int kt = 0; kt < 8; kt++) {
                unsigned b0 = wb[(kt * 8 + tg)     * PW_STRIDE];
                unsigned b1 = wb[(kt * 8 + tg + 4) * PW_STRIDE];
                mma8(c[0][t], a[0][kt], b0, b1);
                mma8(c[1][t], a[1][kt], b0, b1);
            }
        }
    }

    #pragma unroll
    for (int t = 0; t < 12; t++) {
        const int gt = nw * 12 + t;
        const int w  = gt >> 3;
        const int h0 = (gt & 7) * 8 + 2 * tg;
        float* outp = (w == 0) ? g_q : (w == 1) ? g_k : g_v;
        #pragma unroll
        for (int mi = 0; mi < 2; mi++) {
            const int r = rt0 + mw * 32 + mi * 16 + g;
            *(float2*)&outp[(size_t)r       * HSZ + h0] = make_float2(c[mi][t][0], c[mi][t][1]);
            *(float2*)&outp[(size_t)(r + 8) * HSZ + h0] = make_float2(c[mi][t][2], c[mi][t][3]);
        }
    }
}

// ============================================================================
// mma.sync tf32 flash attention. 256 threads = 8 warps, 4(M:32q) x 2(N:64k).
// Double-buffered smem, cp.async K/V streaming (raw fp32 bits -> tf32 mma,
// hardware ignores low mantissa bits). Q frags persistent (RNA-rounded).
// ============================================================================
#define KS_STRIDE 68   /* 272B rows: 16B aligned, banks 4g+tg bijective */
#define VS_STRIDE 72   /* 288B rows: 16B aligned, banks 8tg+g bijective */
#define KS_FLOATS (128*KS_STRIDE)
#define VS_FLOATS (128*VS_STRIDE)
#define BUF_FLOATS (KS_FLOATS + VS_FLOATS)
#define ATTN_SMEM (2 * BUF_FLOATS * 4)
#define OP_STRIDE 66

__global__ __launch_bounds__(256, 1) void attn_kernel(float* __restrict__ outp)
{
    extern __shared__ float smf[];
    const unsigned smem_u = (unsigned)__cvta_generic_to_shared(smf);

    const int tid  = threadIdx.x;
    const int lane = tid & 31;
    const int wid  = tid >> 5;
    const int mw   = wid & 3;
    const int nw   = wid >> 2;
    const int g    = lane >> 2;
    const int tg   = lane & 3;
    const int base = lane & 28;
    const int b    = blockIdx.y;
    const int q0   = blockIdx.x * 128;

    const float qs = 1.4426950408889634f / 32.0f;  // log2(e) * D^-0.5

    const float* kb = g_k + (size_t)b * SEQ * HSZ;
    const float* vb = g_v + (size_t)b * SEQ * HSZ;

    // per-thread cp.async coordinates (8 x 16B for K, 8 for V)
    const int ld_key = tid >> 1;            // 0..127
    const int ld_h   = (tid & 1) * 32;      // two 32-float halves -> 8 chunks of 4

    // ---- persistent Q A-fragments ----
    unsigned qa[2][8][4];
    {
        const float* qb = g_q + ((size_t)b * SEQ + q0) * HSZ;
        #pragma unroll
        for (int mi = 0; mi < 2; mi++) {
            const int r0 = mw * 32 + mi * 16 + g;
            #pragma unroll
            for (int kt = 0; kt < 8; kt++) {
                const int c0 = kt * 8 + tg;
                qa[mi][kt][0] = f2tf(qb[(size_t)r0       * HSZ + c0]     * qs);
                qa[mi][kt][1] = f2tf(qb[(size_t)(r0 + 8) * HSZ + c0]     * qs);
                qa[mi][kt][2] = f2tf(qb[(size_t)r0       * HSZ + c0 + 4] * qs);
                qa[mi][kt][3] = f2tf(qb[(size_t)(r0 + 8) * HSZ + c0 + 4] * qs);
            }
        }
    }

    float o[2][8][4];
    #pragma unroll
    for (int mi = 0; mi < 2; mi++)
        #pragma unroll
        for (int nt = 0; nt < 8; nt++)
            #pragma unroll
            for (int j = 0; j < 4; j++) o[mi][nt][j] = 0.0f;
    float lsum[2][2] = {{0.0f, 0.0f}, {0.0f, 0.0f}};

    // ---- prologue: async-load tile 0 into buffer 0 ----
    {
        const float* kg = kb + (size_t)ld_key * HSZ + ld_h;
        const float* vg = vb + (size_t)ld_key * HSZ + ld_h;
        const unsigned ks = smem_u + (ld_key * KS_STRIDE + ld_h) * 4;
        const unsigned vs = smem_u + (KS_FLOATS + ld_key * VS_STRIDE + ld_h) * 4;
        #pragma unroll
        for (int u = 0; u < 8; u++) {
            CP_ASYNC16(ks + u * 16, kg + u * 4);
            CP_ASYNC16(vs + u * 16, vg + u * 4);
        }
        CP_COMMIT();
    }

    for (int it = 0; it < 32; it++) {
        const unsigned* Ks = (const unsigned*)(smf + (it & 1) * BUF_FLOATS);
        const unsigned* Vs = Ks + KS_FLOATS;

        CP_WAIT0();
        __syncthreads();

        // issue loads for next tile into the other buffer (safe: all warps are
        // past compute(it-1) on that buffer after the barrier above)
        if (it + 1 < 32) {
            const unsigned bufo = ((it + 1) & 1) * BUF_FLOATS * 4;
            const float* kg = kb + (size_t)((it + 1) * 128 + ld_key) * HSZ + ld_h;
            const float* vg = vb + (size_t)((it + 1) * 128 + ld_key) * HSZ + ld_h;
            const unsigned ks = smem_u + bufo + (ld_key * KS_STRIDE + ld_h) * 4;
            const unsigned vs = smem_u + bufo + (KS_FLOATS + ld_key * VS_STRIDE + ld_h) * 4;
            #pragma unroll
            for (int u = 0; u < 8; u++) {
                CP_ASYNC16(ks + u * 16, kg + u * 4);
                CP_ASYNC16(vs + u * 16, vg + u * 4);
            }
            CP_COMMIT();
        }

        // ---- S = Q . K^T : per warp 32 x 64 ----
        float cs[2][8][4];
        #pragma unroll
        for (int nt = 0; nt < 8; nt++) {
            #pragma unroll
            for (int mi = 0; mi < 2; mi++)
                #pragma unroll
                for (int j = 0; j < 4; j++) cs[mi][nt][j] = 0.0f;
            const unsigned* krow = Ks + (nw * 64 + nt * 8 + g) * KS_STRIDE;
            #pragma unroll
            for (int kt = 0; kt < 8; kt++) {
                unsigned b0 = krow[kt * 8 + tg];
                unsigned b1 = krow[kt * 8 + tg + 4];
                mma8(cs[0][nt], qa[0][kt], b0, b1);
                mma8(cs[1][nt], qa[1][kt], b0, b1);
            }
        }

        // ---- softmax (max=0) ----
        #pragma unroll
        for (int mi = 0; mi < 2; mi++)
            #pragma unroll
            for (int nt = 0; nt < 8; nt++)
                #pragma unroll
                for (int j = 0; j < 4; j++) {
                    float pv = ex2f(cs[mi][nt][j]);
                    cs[mi][nt][j] = pv;
                    lsum[mi][j >> 1] += pv;
                }

        // ---- O += P . V ----
        #pragma unroll
        for (int kt = 0; kt < 8; kt++) {
            unsigned pa[2][4];
            #pragma unroll
            for (int mi = 0; mi < 2; mi++) {
                const int s0 = base + (tg >> 1);
                float w0 = __shfl_sync(0xFFFFFFFFu, cs[mi][kt][0], s0);
                float w1 = __shfl_sync(0xFFFFFFFFu, cs[mi][kt][1], s0);
                float w2 = __shfl_sync(0xFFFFFFFFu, cs[mi][kt][2], s0);
                float w3 = __shfl_sync(0xFFFFFFFFu, cs[mi][kt][3], s0);
                float w4 = __shfl_sync(0xFFFFFFFFu, cs[mi][kt][0], s0 + 2);
                float w5 = __shfl_sync(0xFFFFFFFFu, cs[mi][kt][1], s0 + 2);
                float w6 = __shfl_sync(0xFFFFFFFFu, cs[mi][kt][2], s0 + 2);
                float w7 = __shfl_sync(0xFFFFFFFFu, cs[mi][kt][3], s0 + 2);
                pa[mi][0] = __float_as_uint((tg & 1) ? w1 : w0);
                pa[mi][1] = __float_as_uint((tg & 1) ? w3 : w2);
                pa[mi][2] = __float_as_uint((tg & 1) ? w5 : w4);
                pa[mi][3] = __float_as_uint((tg & 1) ? w7 : w6);
            }
            const unsigned* vr0 = Vs + (nw * 64 + kt * 8 + tg)     * VS_STRIDE;
            const unsigned* vr1 = Vs + (nw * 64 + kt * 8 + tg + 4) * VS_STRIDE;
            #pragma unroll
            for (int nt = 0; nt < 8; nt++) {
                unsigned b0 = vr0[nt * 8 + g];
                unsigned b1 = vr1[nt * 8 + g];
                mma8(o[0][nt], pa[0], b0, b1);
                mma8(o[1][nt], pa[1], b0, b1);
            }
        }
    }

    // ---- reduce l within quads ----
    #pragma unroll
    for (int mi = 0; mi < 2; mi++)
        #pragma unroll
        for (int r = 0; r < 2; r++) {
            float v = lsum[mi][r];
            v += __shfl_xor_sync(0xFFFFFFFFu, v, 1);
            v += __shfl_xor_sync(0xFFFFFFFFu, v, 2);
            lsum[mi][r] = v;
        }

    // ---- combine key halves through smem ----
    __syncthreads();
    float* Opart = smf;
    float* lpart = smf + 128 * OP_STRIDE;
    if (nw == 1) {
        #pragma unroll
        for (int mi = 0; mi < 2; mi++) {
            const int r0 = mw * 32 + mi * 16 + g;
            #pragma unroll
            for (int nt = 0; nt < 8; nt++) {
                const int c = nt * 8 + 2 * tg;
                *(float2*)&Opart[r0       * OP_STRIDE + c] = make_float2(o[mi][nt][0], o[mi][nt][1]);
                *(float2*)&Opart[(r0 + 8) * OP_STRIDE + c] = make_float2(o[mi][nt][2], o[mi][nt][3]);
            }
            if (tg == 0) {
                lpart[r0]     = lsum[mi][0];
                lpart[r0 + 8] = lsum[mi][1];
            }
        }
    }
    __syncthreads();
    if (nw == 0) {
        #pragma unroll
        for (int mi = 0; mi < 2; mi++) {
            const int r0 = mw * 32 + mi * 16 + g;
            const float inv0 = 1.0f / (lsum[mi][0] + lpart[r0]);
            const float inv1 = 1.0f / (lsum[mi][1] + lpart[r0 + 8]);
            float* ob0 = outp + ((size_t)b * SEQ + q0 + r0) * HSZ;
            float* ob1 = ob0 + 8 * HSZ;
            #pragma unroll
            for (int nt = 0; nt < 8; nt++) {
                const int c = nt * 8 + 2 * tg;
                float2 p0 = *(const float2*)&Opart[r0       * OP_STRIDE + c];
                float2 p1 = *(const float2*)&Opart[(r0 + 8) * OP_STRIDE + c];
                *(float2*)(ob0 + c) = make_float2((o[mi][nt][0] + p0.x) * inv0,
                                                  (o[mi][nt][1] + p0.y) * inv0);
                *(float2*)(ob1 + c) = make_float2((o[mi][nt][2] + p1.x) * inv1,
                                                  (o[mi][nt][3] + p1.y) * inv1);
            }
        }
    }
}

// ============================================================================
extern "C" void kernel_launch(void* const* d_in, const int* in_sizes, int n_in,
                              void* d_out, int out_size)
{
    (void)in_sizes; (void)n_in; (void)out_size;
    const float* x  = (const float*)d_in[0];
    const float* Wq = (const float*)d_in[1];
    const float* Wk = (const float*)d_in[2];
    const float* Wv = (const float*)d_in[3];
    float* out = (float*)d_out;

    cudaFuncSetAttribute(proj_kernel,
                         cudaFuncAttributeMaxDynamicSharedMemorySize, PROJ_SMEM);
    proj_kernel<<<NROWS / 128, 256, PROJ_SMEM>>>(x, Wq, Wk, Wv);

    cudaFuncSetAttribute(attn_kernel,
                         cudaFuncAttributeMaxDynamicSharedMemorySize, ATTN_SMEM);
    dim3 ga(SEQ / 128, BATCH);
    attn_kernel<<<ga, 256, ATTN_SMEM>>>(out);
}